// round 3
// baseline (speedup 1.0000x reference)
#include <cuda_runtime.h>
#include <cuda_bf16.h>
#include <math.h>

// ---------------------------------------------------------------------------
// BCEDecorrelatedLoss via O(N) + one O(N^2) pass with packed f32x2 (FFMA2) math.
//   ra_i  = sum_j |x_i-x_j| v_j ; rb_i = sum_j |e_i-e_j| v_j ;
//   rab_i = sum_j |x_i-x_j||e_i-e_j| v_j
// then 12 scalar moments -> closed-form num/den (see R0 derivation).
// ---------------------------------------------------------------------------

#define BLK      256
#define IPT      4            // i's per thread (2 packed f32x2 groups)
#define NPACK    (IPT/2)
#define ITILE    (BLK*IPT)
#define JCH      128          // j's per block tile
#define MAXN     8192
#define MAXSPLIT (MAXN/JCH)   // 64
#define RBLOCKS  32

typedef unsigned long long ull;
#define ABSM 0x7fffffff7fffffffULL

#define ADD2(d, a, b) asm("add.rn.f32x2 %0, %1, %2;" : "=l"(d) : "l"(a), "l"(b))
#define MUL2(d, a, b) asm("mul.rn.f32x2 %0, %1, %2;" : "=l"(d) : "l"(a), "l"(b))
#define FMA2(d, a, b, c) asm("fma.rn.f32x2 %0, %1, %2, %3;" : "=l"(d) : "l"(a), "l"(b), "l"(c))
#define PACK2(d, lo, hi) asm("mov.b64 %0, {%1, %2};" : "=l"(d) : "f"(lo), "f"(hi))

__device__ float4 g_p4[MAXSPLIT][MAXN];   // {A, B, AB, pad} partial row sums
__device__ double g_part[RBLOCKS][12];
__device__ unsigned int g_ctr;            // wraps to 0 each full grid pass

__global__ __launch_bounds__(BLK)
void pair_kernel(const float* __restrict__ x, const float* __restrict__ e,
                 const float* __restrict__ w, int n)
{
    // j-tile in smem, pre-duplicated (and pre-negated for x,e) for LDS.64 broadcast
    __shared__ float2 sxn[JCH], sen[JCH], swd[JCH];
    const int js = blockIdx.y;
    const int j0 = js * JCH;
    const int t  = threadIdx.x;

    if (t < JCH) {
        int j = j0 + t;
        bool ok = (j < n);
        float xv = ok ? x[j] : 0.0f;
        float ev = ok ? e[j] : 0.0f;
        float wv = ok ? w[j] : 0.0f;
        sxn[t] = make_float2(-xv, -xv);
        sen[t] = make_float2(-ev, -ev);
        swd[t] = make_float2(wv, wv);
    }
    __syncthreads();

    const int ibase = blockIdx.x * ITILE + t;
    ull xi2[NPACK], ei2[NPACK];
    ull accA[NPACK], accB[NPACK], accAB[NPACK];
#pragma unroll
    for (int g = 0; g < NPACK; g++) {
        int ilo = ibase + (2 * g) * BLK;
        int ihi = ibase + (2 * g + 1) * BLK;
        float xlo = (ilo < n) ? x[ilo] : 0.0f;
        float xhi = (ihi < n) ? x[ihi] : 0.0f;
        float elo = (ilo < n) ? e[ilo] : 0.0f;
        float ehi = (ihi < n) ? e[ihi] : 0.0f;
        PACK2(xi2[g], xlo, xhi);
        PACK2(ei2[g], elo, ehi);
        accA[g] = 0ULL; accB[g] = 0ULL; accAB[g] = 0ULL;
    }

    const ull* pxn = (const ull*)sxn;
    const ull* pen = (const ull*)sen;
    const ull* pwd = (const ull*)swd;

#pragma unroll 8
    for (int k = 0; k < JCH; k++) {
        const ull nxj = pxn[k];
        const ull nej = pen[k];
        const ull wj  = pwd[k];
#pragma unroll
        for (int g = 0; g < NPACK; g++) {
            ull dx, de, awj;
            ADD2(dx, xi2[g], nxj);     // fma pipe (packed)
            ADD2(de, ei2[g], nej);     // fma pipe (packed)
            dx &= ABSM;                // 2x LOP3 -> alu pipe
            de &= ABSM;                // 2x LOP3 -> alu pipe
            MUL2(awj, dx, wj);                  // |dx|*wj
            ADD2(accA[g], accA[g], awj);        // accA += |dx|*wj
            FMA2(accAB[g], awj, de, accAB[g]);  // accAB += |dx|*wj*|de|
            FMA2(accB[g], de, wj, accB[g]);     // accB += |de|*wj
        }
    }

#pragma unroll
    for (int g = 0; g < NPACK; g++) {
        int ilo = ibase + (2 * g) * BLK;
        int ihi = ibase + (2 * g + 1) * BLK;
        float2 a = *(float2*)&accA[g];
        float2 b = *(float2*)&accB[g];
        float2 c = *(float2*)&accAB[g];
        if (ilo < n) g_p4[js][ilo] = make_float4(a.x, b.x, c.x, 0.0f);
        if (ihi < n) g_p4[js][ihi] = make_float4(a.y, b.y, c.y, 0.0f);
    }
}

// Gather partials (64 coalesced LDG.128 per thread), compute 12 moments with
// fp64 accumulation, block-reduce, and the LAST block finalizes the outputs.
__global__ __launch_bounds__(256)
void reduce_kernel(const float* __restrict__ x, const float* __restrict__ y,
                   const float* __restrict__ e, const float* __restrict__ w,
                   float* __restrict__ out, int n, int jsplit)
{
    __shared__ double sm[12][8];
    __shared__ unsigned int s_islast;
    const int tid = threadIdx.x;
    const int gid = blockIdx.x * blockDim.x + tid;
    const int stride = gridDim.x * blockDim.x;

    double s[12];
#pragma unroll
    for (int k = 0; k < 12; k++) s[k] = 0.0;

    for (int i = gid; i < n; i += stride) {
        float ra = 0.f, rb = 0.f, rab = 0.f;
#pragma unroll 8
        for (int js = 0; js < jsplit; js++) {
            float4 p = g_p4[js][i];
            ra += p.x; rb += p.y; rab += p.z;
        }
        float vi = w[i];
        float xi = x[i];
        float ei = e[i];
        float yi = y[i];

        float sp  = fmaxf(xi, 0.0f) + log1pf(expf(-fabsf(xi)));
        float bce = (sp - xi * yi) * vi;

        s[0]  += (double)vi;
        s[1]  += (double)(vi * ra);
        s[2]  += (double)(vi * rb);
        s[3]  += (double)(vi * rab);
        s[4]  += (double)(vi * ra * rb);
        s[5]  += (double)(vi * ra * ra);
        s[6]  += (double)(vi * rb * rb);
        s[7]  += (double)(vi * xi);
        s[8]  += (double)(vi * xi * xi);
        s[9]  += (double)(vi * ei);
        s[10] += (double)(vi * ei * ei);
        s[11] += (double)bce;
    }

#pragma unroll
    for (int k = 0; k < 12; k++) {
        double v = s[k];
        for (int o = 16; o > 0; o >>= 1)
            v += __shfl_down_sync(0xffffffffu, v, o);
        if ((tid & 31) == 0) sm[k][tid >> 5] = v;
    }
    __syncthreads();
    if (tid < 12) {
        double v = 0.0;
#pragma unroll
        for (int wi = 0; wi < 8; wi++) v += sm[tid][wi];
        g_part[blockIdx.x][tid] = v;
    }
    // last-block finalize (counter wraps to 0 each grid pass -> graph-safe)
    __threadfence();
    __syncthreads();
    if (tid == 0) {
        unsigned int old = atomicInc(&g_ctr, RBLOCKS - 1);
        s_islast = (old == RBLOCKS - 1) ? 1u : 0u;
    }
    __syncthreads();
    if (s_islast && tid == 0) {
        double tot[12];
#pragma unroll
        for (int k = 0; k < 12; k++) {
            double v = 0.0;
            for (int p = 0; p < RBLOCKS; p++) v += g_part[p][k];
            tot[k] = v;
        }
        double sw  = tot[0];
        double Ra  = tot[1],  Rb  = tot[2],  Rab = tot[3];
        double P   = tot[4],  Qa  = tot[5],  Qb  = tot[6];
        double Vx  = tot[7],  Vx2 = tot[8];
        double Ve  = tot[9],  Ve2 = tot[10];
        double Sbce = tot[11];

        double isw  = 1.0 / sw;
        double isw2 = isw * isw;
        double isw3 = isw2 * isw;
        double isw4 = isw2 * isw2;

        double num  = Rab * isw2 - 2.0 * P * isw3 + Ra * Rb * isw4;
        double dena = 2.0 * Vx2 * isw - 2.0 * Vx * Vx * isw2
                    - 2.0 * Qa * isw3 + Ra * Ra * isw4;
        double denb = 2.0 * Ve2 * isw - 2.0 * Ve * Ve * isw2
                    - 2.0 * Qb * isw3 + Rb * Rb * isw4;

        double disco = num / sqrt(dena * denb);
        double bce   = Sbce / (double)n;

        out[0] = (float)bce;
        out[1] = (float)disco;
        out[2] = (float)(bce + 0.1 * disco);
    }
}

extern "C" void kernel_launch(void* const* d_in, const int* in_sizes, int n_in,
                              void* d_out, int out_size)
{
    const float* x = (const float*)d_in[0];   // outputs (logits)
    const float* y = (const float*)d_in[1];   // labels
    const float* e = (const float*)d_in[2];   // event
    const float* w = (const float*)d_in[3];   // weights
    float* out = (float*)d_out;
    const int n = in_sizes[0];

    int itiles = (n + ITILE - 1) / ITILE;     // 8 for n=8192
    int jsplit = (n + JCH - 1) / JCH;         // 64 for n=8192
    if (jsplit > MAXSPLIT) jsplit = MAXSPLIT;

    dim3 grid(itiles, jsplit);
    pair_kernel<<<grid, BLK>>>(x, e, w, n);
    reduce_kernel<<<RBLOCKS, 256>>>(x, y, e, w, out, n, jsplit);
}

// round 4
// speedup vs baseline: 1.1351x; 1.1351x over previous
#include <cuda_runtime.h>
#include <cuda_bf16.h>
#include <math.h>

// ---------------------------------------------------------------------------
// BCEDecorrelatedLoss via O(N) + one O(N^2) pass with packed f32x2 (FFMA2) math.
//   ra_i  = sum_j |x_i-x_j| v_j ; rb_i = sum_j |e_i-e_j| v_j ;
//   rab_i = sum_j |x_i-x_j||e_i-e_j| v_j
// then 12 scalar moments -> closed-form num/den.
// ---------------------------------------------------------------------------

#define BLK      256
#define IPT      8            // i's per thread (4 packed f32x2 groups)
#define NPACK    (IPT/2)
#define ITILE    (BLK*IPT)    // 2048
#define JCH      128          // j's per block tile
#define MAXN     8192
#define MAXSPLIT (MAXN/JCH)   // 64
#define RBLOCKS  256          // reduce grid

typedef unsigned long long ull;
#define ABSM 0x7fffffff7fffffffULL

#define ADD2(d, a, b) asm("add.rn.f32x2 %0, %1, %2;" : "=l"(d) : "l"(a), "l"(b))
#define MUL2(d, a, b) asm("mul.rn.f32x2 %0, %1, %2;" : "=l"(d) : "l"(a), "l"(b))
#define FMA2(d, a, b, c) asm("fma.rn.f32x2 %0, %1, %2, %3;" : "=l"(d) : "l"(a), "l"(b), "l"(c))
#define PACK2(d, lo, hi) asm("mov.b64 %0, {%1, %2};" : "=l"(d) : "f"(lo), "f"(hi))

__device__ float4 g_p4[MAXSPLIT][MAXN];   // {A, B, AB, pad} partial row sums
__device__ double g_part[RBLOCKS][12];
__device__ unsigned int g_ctr;            // wraps to 0 each full grid pass

__global__ __launch_bounds__(BLK)
void pair_kernel(const float* __restrict__ x, const float* __restrict__ e,
                 const float* __restrict__ w, int n)
{
    // j-tile in smem, duplicated lanes (x,e negated) for LDS.64 broadcast
    __shared__ float2 sxn[JCH], sen[JCH], swd[JCH];
    const int js = blockIdx.y;
    const int j0 = js * JCH;
    const int t  = threadIdx.x;

    if (t < JCH) {
        int j = j0 + t;
        bool ok = (j < n);
        float xv = ok ? x[j] : 0.0f;
        float ev = ok ? e[j] : 0.0f;
        float wv = ok ? w[j] : 0.0f;
        sxn[t] = make_float2(-xv, -xv);
        sen[t] = make_float2(-ev, -ev);
        swd[t] = make_float2(wv, wv);
    }
    __syncthreads();

    const int ibase = blockIdx.x * ITILE + t;
    ull xi2[NPACK], ei2[NPACK];
    ull accA[NPACK], accB[NPACK], accAB[NPACK];
#pragma unroll
    for (int g = 0; g < NPACK; g++) {
        int ilo = ibase + (2 * g) * BLK;
        int ihi = ibase + (2 * g + 1) * BLK;
        float xlo = (ilo < n) ? x[ilo] : 0.0f;
        float xhi = (ihi < n) ? x[ihi] : 0.0f;
        float elo = (ilo < n) ? e[ilo] : 0.0f;
        float ehi = (ihi < n) ? e[ihi] : 0.0f;
        PACK2(xi2[g], xlo, xhi);
        PACK2(ei2[g], elo, ehi);
        accA[g] = 0ULL; accB[g] = 0ULL; accAB[g] = 0ULL;
    }

    const ull* pxn = (const ull*)sxn;
    const ull* pen = (const ull*)sen;
    const ull* pwd = (const ull*)swd;

#pragma unroll 4
    for (int k = 0; k < JCH; k++) {
        const ull nxj = pxn[k];
        const ull nej = pen[k];
        const ull wj  = pwd[k];
#pragma unroll
        for (int g = 0; g < NPACK; g++) {
            ull dx, de, awj;
            ADD2(dx, xi2[g], nxj);     // packed fma pipe
            ADD2(de, ei2[g], nej);
            dx &= ABSM;                // LOP3 -> alu pipe
            de &= ABSM;
            MUL2(awj, dx, wj);                  // |dx|*wj
            ADD2(accA[g], accA[g], awj);        // accA += |dx|*wj
            FMA2(accAB[g], awj, de, accAB[g]);  // accAB += |dx|*wj*|de|
            FMA2(accB[g], de, wj, accB[g]);     // accB += |de|*wj
        }
    }

#pragma unroll
    for (int g = 0; g < NPACK; g++) {
        int ilo = ibase + (2 * g) * BLK;
        int ihi = ibase + (2 * g + 1) * BLK;
        float2 a = *(float2*)&accA[g];
        float2 b = *(float2*)&accB[g];
        float2 c = *(float2*)&accAB[g];
        if (ilo < n) g_p4[js][ilo] = make_float4(a.x, b.x, c.x, 0.0f);
        if (ihi < n) g_p4[js][ihi] = make_float4(a.y, b.y, c.y, 0.0f);
    }
}

// Wide gather: 8 threads per row i (each loads 8 independent float4 partials),
// shuffle-combine across the 8 lanes, compute 12 fp64 moments, block-reduce,
// last block finalizes (counter wraps each pass -> graph-safe).
__global__ __launch_bounds__(256)
void reduce_kernel(const float* __restrict__ x, const float* __restrict__ y,
                   const float* __restrict__ e, const float* __restrict__ w,
                   float* __restrict__ out, int n, int jsplit)
{
    __shared__ double sm[12][8];
    __shared__ unsigned int s_islast;
    const int tid = threadIdx.x;
    const int gid = blockIdx.x * blockDim.x + tid;

    const int i  = gid >> 3;          // row this thread helps with
    const int jc = gid & 7;           // which 1/8 of the splits
    const int per = (jsplit + 7) / 8; // splits per lane (8 for jsplit=64)

    float ra = 0.f, rb = 0.f, rab = 0.f;
    if (i < n) {
#pragma unroll 8
        for (int u = 0; u < per; u++) {
            int js = jc * per + u;
            if (js < jsplit) {
                float4 p = g_p4[js][i];
                ra += p.x; rb += p.y; rab += p.z;
            }
        }
    }
    // combine the 8 lanes that share row i (consecutive lanes)
#pragma unroll
    for (int o = 4; o > 0; o >>= 1) {
        ra  += __shfl_down_sync(0xffffffffu, ra,  o, 8);
        rb  += __shfl_down_sync(0xffffffffu, rb,  o, 8);
        rab += __shfl_down_sync(0xffffffffu, rab, o, 8);
    }

    double s[12];
#pragma unroll
    for (int k = 0; k < 12; k++) s[k] = 0.0;

    if (jc == 0 && i < n) {
        float vi = w[i];
        float xi = x[i];
        float ei = e[i];
        float yi = y[i];
        float sp  = fmaxf(xi, 0.0f) + log1pf(expf(-fabsf(xi)));
        float bce = (sp - xi * yi) * vi;

        s[0]  = (double)vi;
        s[1]  = (double)(vi * ra);
        s[2]  = (double)(vi * rb);
        s[3]  = (double)(vi * rab);
        s[4]  = (double)(vi * ra * rb);
        s[5]  = (double)(vi * ra * ra);
        s[6]  = (double)(vi * rb * rb);
        s[7]  = (double)(vi * xi);
        s[8]  = (double)(vi * xi * xi);
        s[9]  = (double)(vi * ei);
        s[10] = (double)(vi * ei * ei);
        s[11] = (double)bce;
    }

#pragma unroll
    for (int k = 0; k < 12; k++) {
        double v = s[k];
        for (int o = 16; o > 0; o >>= 1)
            v += __shfl_down_sync(0xffffffffu, v, o);
        if ((tid & 31) == 0) sm[k][tid >> 5] = v;
    }
    __syncthreads();
    if (tid < 12) {
        double v = 0.0;
#pragma unroll
        for (int wi = 0; wi < 8; wi++) v += sm[tid][wi];
        g_part[blockIdx.x][tid] = v;
    }
    __threadfence();
    __syncthreads();
    if (tid == 0) {
        unsigned int old = atomicInc(&g_ctr, RBLOCKS - 1);
        s_islast = (old == RBLOCKS - 1) ? 1u : 0u;
    }
    __syncthreads();
    if (s_islast) {
        // parallel final reduce: thread tid owns partial row tid
        double t2[12];
#pragma unroll
        for (int k = 0; k < 12; k++) t2[k] = g_part[tid][k];
#pragma unroll
        for (int k = 0; k < 12; k++) {
            double v = t2[k];
            for (int o = 16; o > 0; o >>= 1)
                v += __shfl_down_sync(0xffffffffu, v, o);
            if ((tid & 31) == 0) sm[k][tid >> 5] = v;
        }
        __syncthreads();
        if (tid == 0) {
            double tot[12];
#pragma unroll
            for (int k = 0; k < 12; k++) {
                double v = 0.0;
#pragma unroll
                for (int wi = 0; wi < 8; wi++) v += sm[k][wi];
                tot[k] = v;
            }
            double sw  = tot[0];
            double Ra  = tot[1],  Rb  = tot[2],  Rab = tot[3];
            double P   = tot[4],  Qa  = tot[5],  Qb  = tot[6];
            double Vx  = tot[7],  Vx2 = tot[8];
            double Ve  = tot[9],  Ve2 = tot[10];
            double Sbce = tot[11];

            double isw  = 1.0 / sw;
            double isw2 = isw * isw;
            double isw3 = isw2 * isw;
            double isw4 = isw2 * isw2;

            double num  = Rab * isw2 - 2.0 * P * isw3 + Ra * Rb * isw4;
            double dena = 2.0 * Vx2 * isw - 2.0 * Vx * Vx * isw2
                        - 2.0 * Qa * isw3 + Ra * Ra * isw4;
            double denb = 2.0 * Ve2 * isw - 2.0 * Ve * Ve * isw2
                        - 2.0 * Qb * isw3 + Rb * Rb * isw4;

            double disco = num / sqrt(dena * denb);
            double bce   = Sbce / (double)n;

            out[0] = (float)bce;
            out[1] = (float)disco;
            out[2] = (float)(bce + 0.1 * disco);
        }
    }
}

extern "C" void kernel_launch(void* const* d_in, const int* in_sizes, int n_in,
                              void* d_out, int out_size)
{
    const float* x = (const float*)d_in[0];   // outputs (logits)
    const float* y = (const float*)d_in[1];   // labels
    const float* e = (const float*)d_in[2];   // event
    const float* w = (const float*)d_in[3];   // weights
    float* out = (float*)d_out;
    const int n = in_sizes[0];

    int itiles = (n + ITILE - 1) / ITILE;     // 4 for n=8192
    int jsplit = (n + JCH - 1) / JCH;         // 64 for n=8192
    if (jsplit > MAXSPLIT) jsplit = MAXSPLIT;

    dim3 grid(itiles, jsplit);
    pair_kernel<<<grid, BLK>>>(x, e, w, n);
    reduce_kernel<<<RBLOCKS, 256>>>(x, y, e, w, out, n, jsplit);
}

// round 5
// speedup vs baseline: 1.4318x; 1.2614x over previous
#include <cuda_runtime.h>
#include <cuda_bf16.h>
#include <math.h>

// ---------------------------------------------------------------------------
// BCEDecorrelatedLoss via O(N) + one O(N^2) pass with packed f32x2 (FFMA2) math.
//   ra_i  = sum_j |x_i-x_j| v_j ; rb_i = sum_j |e_i-e_j| v_j ;
//   rab_i = sum_j |x_i-x_j||e_i-e_j| v_j
// then 12 scalar moments -> closed-form num/den.
// ---------------------------------------------------------------------------

#define BLK      256
#define IPT      4            // i's per thread (2 packed f32x2 groups)
#define NPACK    (IPT/2)
#define ITILE    (BLK*IPT)    // 1024
#define JCH      128          // j's per block tile
#define MAXN     8192
#define MAXSPLIT (MAXN/JCH)   // 64
#define RBLOCKS  256          // reduce grid (MAXN/32)

typedef unsigned long long ull;
#define ABSM 0x7fffffff7fffffffULL

#define ADD2(d, a, b) asm("add.rn.f32x2 %0, %1, %2;" : "=l"(d) : "l"(a), "l"(b))
#define MUL2(d, a, b) asm("mul.rn.f32x2 %0, %1, %2;" : "=l"(d) : "l"(a), "l"(b))
#define FMA2(d, a, b, c) asm("fma.rn.f32x2 %0, %1, %2, %3;" : "=l"(d) : "l"(a), "l"(b), "l"(c))
#define PACK2(d, lo, hi) asm("mov.b64 %0, {%1, %2};" : "=l"(d) : "f"(lo), "f"(hi))

__device__ float4 g_p4[MAXSPLIT][MAXN];   // {A, B, AB, pad} partial row sums
__device__ double g_part[RBLOCKS][12];
__device__ unsigned int g_ctr;            // wraps to 0 each full grid pass

__global__ __launch_bounds__(BLK)
void pair_kernel(const float* __restrict__ x, const float* __restrict__ e,
                 const float* __restrict__ w, int n)
{
    // j-tile in smem, duplicated lanes (x,e negated) for LDS.64 broadcast
    __shared__ float2 sxn[JCH], sen[JCH], swd[JCH];
    const int js = blockIdx.y;
    const int j0 = js * JCH;
    const int t  = threadIdx.x;

    if (t < JCH) {
        int j = j0 + t;
        bool ok = (j < n);
        float xv = ok ? x[j] : 0.0f;
        float ev = ok ? e[j] : 0.0f;
        float wv = ok ? w[j] : 0.0f;
        sxn[t] = make_float2(-xv, -xv);
        sen[t] = make_float2(-ev, -ev);
        swd[t] = make_float2(wv, wv);
    }
    __syncthreads();

    const int ibase = blockIdx.x * ITILE + t;
    ull xi2[NPACK], ei2[NPACK];
    ull accA[NPACK], accB[NPACK], accAB[NPACK];
#pragma unroll
    for (int g = 0; g < NPACK; g++) {
        int ilo = ibase + (2 * g) * BLK;
        int ihi = ibase + (2 * g + 1) * BLK;
        float xlo = (ilo < n) ? x[ilo] : 0.0f;
        float xhi = (ihi < n) ? x[ihi] : 0.0f;
        float elo = (ilo < n) ? e[ilo] : 0.0f;
        float ehi = (ihi < n) ? e[ihi] : 0.0f;
        PACK2(xi2[g], xlo, xhi);
        PACK2(ei2[g], elo, ehi);
        accA[g] = 0ULL; accB[g] = 0ULL; accAB[g] = 0ULL;
    }

    const ull* pxn = (const ull*)sxn;
    const ull* pen = (const ull*)sen;
    const ull* pwd = (const ull*)swd;

#pragma unroll 8
    for (int k = 0; k < JCH; k++) {
        const ull nxj = pxn[k];
        const ull nej = pen[k];
        const ull wj  = pwd[k];
#pragma unroll
        for (int g = 0; g < NPACK; g++) {
            ull dx, de, awj;
            ADD2(dx, xi2[g], nxj);     // packed fma pipe
            ADD2(de, ei2[g], nej);
            dx &= ABSM;                // LOP3 -> alu pipe
            de &= ABSM;
            MUL2(awj, dx, wj);                  // |dx|*wj
            ADD2(accA[g], accA[g], awj);        // accA += |dx|*wj
            FMA2(accAB[g], awj, de, accAB[g]);  // accAB += |dx|*wj*|de|
            FMA2(accB[g], de, wj, accB[g]);     // accB += |de|*wj
        }
    }

#pragma unroll
    for (int g = 0; g < NPACK; g++) {
        int ilo = ibase + (2 * g) * BLK;
        int ihi = ibase + (2 * g + 1) * BLK;
        float2 a = *(float2*)&accA[g];
        float2 b = *(float2*)&accB[g];
        float2 c = *(float2*)&accAB[g];
        if (ilo < n) g_p4[js][ilo] = make_float4(a.x, b.x, c.x, 0.0f);
        if (ihi < n) g_p4[js][ihi] = make_float4(a.y, b.y, c.y, 0.0f);
    }
}

// Coalesced wide reduce: block b owns 32 consecutive i's. Warp w (0..7) owns
// js-chunk [8w, 8w+8): each lane loads 8 independent, fully-coalesced float4s
// (g_p4[js][i0+lane] -> 512B contiguous per warp per load, MLP=8).
// Cross-warp combine in smem; warp 0 computes 12 fp64 moments; block-reduce;
// LAST block (atomicInc wrap -> graph-safe) finalizes the 3 outputs.
__global__ __launch_bounds__(256)
void reduce_kernel(const float* __restrict__ x, const float* __restrict__ y,
                   const float* __restrict__ e, const float* __restrict__ w,
                   float* __restrict__ out, int n, int jsplit)
{
    __shared__ float sA[8][32], sB[8][32], sAB[8][32];
    __shared__ double sm[12][8];
    __shared__ unsigned int s_islast;
    const int tid  = threadIdx.x;
    const int wid  = tid >> 5;
    const int lane = tid & 31;
    const int i0   = blockIdx.x * 32;
    const int i    = i0 + lane;

    float ra = 0.f, rb = 0.f, rab = 0.f;
    const int jsbase = wid * 8;
    if (i < n) {
#pragma unroll
        for (int u = 0; u < 8; u++) {
            int js = jsbase + u;
            if (js < jsplit) {
                float4 p = g_p4[js][i];
                ra += p.x; rb += p.y; rab += p.z;
            }
        }
    }
    sA[wid][lane] = ra; sB[wid][lane] = rb; sAB[wid][lane] = rab;
    __syncthreads();

    double s[12];
#pragma unroll
    for (int k = 0; k < 12; k++) s[k] = 0.0;

    if (wid == 0 && i < n) {
        float fra = 0.f, frb = 0.f, frab = 0.f;
#pragma unroll
        for (int ww = 0; ww < 8; ww++) {
            fra += sA[ww][lane]; frb += sB[ww][lane]; frab += sAB[ww][lane];
        }
        float vi = w[i];
        float xi = x[i];
        float ei = e[i];
        float yi = y[i];
        float sp  = fmaxf(xi, 0.0f) + log1pf(expf(-fabsf(xi)));
        float bce = (sp - xi * yi) * vi;

        s[0]  = (double)vi;
        s[1]  = (double)(vi * fra);
        s[2]  = (double)(vi * frb);
        s[3]  = (double)(vi * frab);
        s[4]  = (double)(vi * fra * frb);
        s[5]  = (double)(vi * fra * fra);
        s[6]  = (double)(vi * frb * frb);
        s[7]  = (double)(vi * xi);
        s[8]  = (double)(vi * xi * xi);
        s[9]  = (double)(vi * ei);
        s[10] = (double)(vi * ei * ei);
        s[11] = (double)bce;
    }

    // warp 0 holds all nonzero contributions; shuffle-reduce and store
    if (wid == 0) {
#pragma unroll
        for (int k = 0; k < 12; k++) {
            double v = s[k];
            for (int o = 16; o > 0; o >>= 1)
                v += __shfl_down_sync(0xffffffffu, v, o);
            if (lane == 0) g_part[blockIdx.x][k] = v;
        }
    }
    __threadfence();
    __syncthreads();
    if (tid == 0) {
        unsigned int old = atomicInc(&g_ctr, RBLOCKS - 1);
        s_islast = (old == RBLOCKS - 1) ? 1u : 0u;
    }
    __syncthreads();
    if (s_islast) {
        // all 256 threads: thread tid owns partial row tid
        double t2[12];
#pragma unroll
        for (int k = 0; k < 12; k++) t2[k] = g_part[tid][k];
#pragma unroll
        for (int k = 0; k < 12; k++) {
            double v = t2[k];
            for (int o = 16; o > 0; o >>= 1)
                v += __shfl_down_sync(0xffffffffu, v, o);
            if ((tid & 31) == 0) sm[k][tid >> 5] = v;
        }
        __syncthreads();
        if (tid == 0) {
            double tot[12];
#pragma unroll
            for (int k = 0; k < 12; k++) {
                double v = 0.0;
#pragma unroll
                for (int wi = 0; wi < 8; wi++) v += sm[k][wi];
                tot[k] = v;
            }
            double sw  = tot[0];
            double Ra  = tot[1],  Rb  = tot[2],  Rab = tot[3];
            double P   = tot[4],  Qa  = tot[5],  Qb  = tot[6];
            double Vx  = tot[7],  Vx2 = tot[8];
            double Ve  = tot[9],  Ve2 = tot[10];
            double Sbce = tot[11];

            double isw  = 1.0 / sw;
            double isw2 = isw * isw;
            double isw3 = isw2 * isw;
            double isw4 = isw2 * isw2;

            double num  = Rab * isw2 - 2.0 * P * isw3 + Ra * Rb * isw4;
            double dena = 2.0 * Vx2 * isw - 2.0 * Vx * Vx * isw2
                        - 2.0 * Qa * isw3 + Ra * Ra * isw4;
            double denb = 2.0 * Ve2 * isw - 2.0 * Ve * Ve * isw2
                        - 2.0 * Qb * isw3 + Rb * Rb * isw4;

            double disco = num / sqrt(dena * denb);
            double bce   = Sbce / (double)n;

            out[0] = (float)bce;
            out[1] = (float)disco;
            out[2] = (float)(bce + 0.1 * disco);
        }
    }
}

extern "C" void kernel_launch(void* const* d_in, const int* in_sizes, int n_in,
                              void* d_out, int out_size)
{
    const float* x = (const float*)d_in[0];   // outputs (logits)
    const float* y = (const float*)d_in[1];   // labels
    const float* e = (const float*)d_in[2];   // event
    const float* w = (const float*)d_in[3];   // weights
    float* out = (float*)d_out;
    const int n = in_sizes[0];

    int itiles = (n + ITILE - 1) / ITILE;     // 8 for n=8192
    int jsplit = (n + JCH - 1) / JCH;         // 64 for n=8192
    if (jsplit > MAXSPLIT) jsplit = MAXSPLIT;

    dim3 grid(itiles, jsplit);
    pair_kernel<<<grid, BLK>>>(x, e, w, n);
    reduce_kernel<<<RBLOCKS, 256>>>(x, y, e, w, out, n, jsplit);
}